// round 16
// baseline (speedup 1.0000x reference)
#include <cuda_runtime.h>
#include <cstdint>

// ---------------------------------------------------------------------------
// Fully fused GRU acoustic model (single kernel):
//   encoder GRU(13->300) T=2048, fc+relu, decoder GRU(300->13) T=2048.
//
// 16 clusters x 8 CTAs x 512 thr. Cluster = 4 batches. Encoder: each thread
// owns TWO gate-rows x one 38-k chunk of Whh packed f32x2 in registers; h
// loaded via LDS.64 broadcast. Per step: stage1 -> syncthreads -> tail
// (warps 0-4: reduce + gates, then PAIRED u64 DSMEM pushes built via
// shfl.xor(4) -- halves remote-store count) -> cluster arrive -> shadow
// gi(t+1) + x(t+2) prefetch on warps 5-9/10 -> cluster wait.
// ---------------------------------------------------------------------------

#define KB   64
#define KT   2048
#define KF   13
#define KH   300
#define KCL  8      // CTAs per cluster
#define KBPC 4      // batches per cluster
#define KU   38     // hidden units per CTA (rank 7 uses 34)
#define KROWS 114   // 3 * KU gate rows per CTA
#define KTHR 512
#define KHP  304    // padded k extent per batch row (8 chunks * 38)
#define NCH  8      // k-chunks
#define CK   38     // k per chunk
#define CPAIR 19    // k-pairs per chunk
#define PSTR 36     // part row stride in floats

typedef unsigned long long u64t;

struct EncSmem {
    float h[2][KBPC][KHP];       // double-buffered hidden, [buf][batch][k]
    float part[KROWS][PSTR];     // partials [row][chunk*4+batch]; reused as
                                 // emb/dgi scratch post-encoder
    float WihT[16][128];         // input weights transposed [f][row]
    float gis[2][120][KBPC];     // double-buffered gate-input terms:
                                 //   r,z rows: gi + bih + bhh
                                 //   n rows:   gi + bih
    float bsumF[128];            // r,z rows: bih+bhh ; n rows: bih
    float bhhN[64];              // bhh for n rows (jl)
    float xs[2][KBPC][16];       // x_t ring (parity by step)
};

__device__ __forceinline__ float sigm_fast(float v) {
    return __fdividef(1.0f, 1.0f + __expf(-v));
}
__device__ __forceinline__ float tanh_fast(float v) {
    return __fdividef(2.0f, 1.0f + __expf(-2.0f * v)) - 1.0f;
}
__device__ __forceinline__ void cluster_sync() {
    asm volatile("barrier.cluster.arrive.aligned;\n\t"
                 "barrier.cluster.wait.aligned;" ::: "memory");
}
__device__ __forceinline__ uint32_t smem_u32(const void* p) {
    uint32_t a;
    asm("{ .reg .u64 t; cvta.to.shared.u64 t, %1; cvt.u32.u64 %0, t; }"
        : "=r"(a) : "l"(p));
    return a;
}
__device__ __forceinline__ uint32_t mapa_u32(uint32_t laddr, uint32_t rank) {
    uint32_t ra;
    asm("mapa.shared::cluster.u32 %0, %1, %2;" : "=r"(ra) : "r"(laddr), "r"(rank));
    return ra;
}
__device__ __forceinline__ void st_cluster_u64(uint32_t addr, u64t v) {
    asm volatile("st.shared::cluster.b64 [%0], %1;" :: "r"(addr), "l"(v) : "memory");
}
__device__ __forceinline__ u64t lds_b64(uint32_t addr) {
    u64t v;
    asm volatile("ld.shared.b64 %0, [%1];" : "=l"(v) : "r"(addr));
    return v;
}
__device__ __forceinline__ u64t pack2(float lo, float hi) {
    u64t v;
    asm("mov.b64 %0, {%1, %2};" : "=l"(v) : "f"(lo), "f"(hi));
    return v;
}
__device__ __forceinline__ float hadd2(u64t v) {
    float lo, hi;
    asm("mov.b64 {%0, %1}, %2;" : "=f"(lo), "=f"(hi) : "l"(v));
    return lo + hi;
}
__device__ __forceinline__ void fma2(u64t& d, u64t a, u64t b) {
    asm("fma.rn.f32x2 %0, %1, %2, %0;" : "+l"(d) : "l"(a), "l"(b));
}

__global__ void __cluster_dims__(KCL, 1, 1) __launch_bounds__(KTHR, 1)
enc_kernel(const float* __restrict__ x,    const float* __restrict__ Wih,
           const float* __restrict__ Whh,  const float* __restrict__ bih,
           const float* __restrict__ bhh,
           const float* __restrict__ fcW,  const float* __restrict__ fcb,
           const float* __restrict__ dWih, const float* __restrict__ dWhh,
           const float* __restrict__ dbih, const float* __restrict__ dbhh,
           float* __restrict__ out, int writeEmb)
{
    __shared__ __align__(16) EncSmem S;
    const int tid     = threadIdx.x;
    const int cluster = blockIdx.x / KCL;
    const int rank    = blockIdx.x % KCL;
    const int u0      = rank * KU;
    const int ucnt    = (KH - u0 < KU) ? (KH - u0) : KU;

    const int rp = tid & 63;       // row-pair index, active < 57
    const int c  = tid >> 6;       // k-chunk 0..7 (uniform per warp)
    const int r0 = 2 * rp;         // gate rows r0, r0+1
    const int k0 = c * CK;

    // ---- init smem ----
    for (int i = tid; i < 2 * KBPC * KHP; i += KTHR) (&S.h[0][0][0])[i] = 0.f;
    for (int i = tid; i < 16 * 128; i += KTHR) (&S.WihT[0][0])[i] = 0.f;
    for (int i = tid; i < 128; i += KTHR) S.bsumF[i] = 0.f;
    for (int i = tid; i < 64; i += KTHR) S.bhhN[i] = 0.f;
    __syncthreads();

    for (int i = tid; i < 3 * ucnt * KF; i += KTHR) {
        const int f  = i % KF;
        const int rr = i / KF;
        const int g = rr / ucnt, jl = rr % ucnt;
        S.WihT[f][g * KU + jl] = Wih[(size_t)(g * KH + u0 + jl) * KF + f];
    }
    if (tid < KROWS) {
        const int g = tid / KU, jl = tid % KU;
        if (jl < ucnt) {
            const float bi = bih[g * KH + u0 + jl];
            const float bh = bhh[g * KH + u0 + jl];
            if (g < 2) S.bsumF[tid] = bi + bh;   // r,z: fold both biases
            else       { S.bsumF[tid] = bi; S.bhhN[jl] = bh; }  // n: split
        }
    }
    // xs[0] = x_0 (for gis[0] precompute), xs[1] = x_1 (step-0 shadow gi)
    if (tid < KBPC * KF) {
        const int m = tid / KF, f = tid % KF;
        S.xs[0][m][f] = x[((size_t)(cluster * KBPC + m) * KT + 0) * KF + f];
    } else if (tid >= 160 && tid < 160 + KBPC * KF) {
        const int idx = tid - 160;
        const int m = idx / KF, f = idx % KF;
        S.xs[1][m][f] = x[((size_t)(cluster * KBPC + m) * KT + 1) * KF + f];
    }

    // ---- load this thread's TWO gate-rows of packed Whh k-pairs ----
    u64t Wa[CPAIR], Wb[CPAIR];
    {
        const int ga = r0 / KU,       jla = r0 % KU;
        const int gb = (r0 + 1) / KU, jlb = (r0 + 1) % KU;
        const bool actA = (rp < 57) && (r0 < KROWS)     && (jla < ucnt);
        const bool actB = (rp < 57) && (r0 + 1 < KROWS) && (jlb < ucnt);
        const float* wrA = actA ? (Whh + (size_t)(ga * KH + u0 + jla) * KH) : Whh;
        const float* wrB = actB ? (Whh + (size_t)(gb * KH + u0 + jlb) * KH) : Whh;
        #pragma unroll
        for (int i = 0; i < CPAIR; ++i) {
            const int k = k0 + 2 * i;
            float a0 = 0.f, a1 = 0.f, b0 = 0.f, b1 = 0.f;
            if (actA && k < KH)     a0 = wrA[k];
            if (actA && k + 1 < KH) a1 = wrA[k + 1];
            if (actB && k < KH)     b0 = wrB[k];
            if (actB && k + 1 < KH) b1 = wrB[k + 1];
            Wa[i] = pack2(a0, a1);
            Wb[i] = pack2(b0, b1);
        }
    }
    __syncthreads();

    // ---- precompute gis[0] from xs[0] ----
    if (tid < KBPC * KU) {
        const int jl = tid >> 2, m = tid & 3;
        if (jl < ucnt) {
            const float* xr = S.xs[0][m];
            float gr = S.bsumF[jl], gz = S.bsumF[KU + jl], gn = S.bsumF[2 * KU + jl];
            #pragma unroll
            for (int f = 0; f < KF; ++f) {
                const float xf = xr[f];
                gr = fmaf(S.WihT[f][jl], xf, gr);
                gz = fmaf(S.WihT[f][KU + jl], xf, gz);
                gn = fmaf(S.WihT[f][2 * KU + jl], xf, gn);
            }
            S.gis[0][jl][m] = gr;
            S.gis[0][KU + jl][m] = gz;
            S.gis[0][2 * KU + jl][m] = gn;
        }
    }

    // ---- hoisted DSMEM peer base addresses + step offsets ----
    const uint32_t hbaseL = smem_u32(&S.h[0][0][0]);
    uint32_t R0 = mapa_u32(hbaseL, 0), R1 = mapa_u32(hbaseL, 1),
             R2 = mapa_u32(hbaseL, 2), R3 = mapa_u32(hbaseL, 3),
             R4 = mapa_u32(hbaseL, 4), R5 = mapa_u32(hbaseL, 5),
             R6 = mapa_u32(hbaseL, 6), R7 = mapa_u32(hbaseL, 7);
    const int jl_t = tid >> 2, m_t = tid & 3;   // tail mapping (jl_t 0..39)
    // u64 pair-store offsets (even jl lanes store units {jl, jl+1})
    const uint32_t offA = ((KBPC + m_t) * KHP + u0 + jl_t) * 4;  // write h[1]
    const uint32_t offB = ((m_t) * KHP + u0 + jl_t) * 4;         // write h[0]

    __syncthreads();
    cluster_sync();   // peers' h buffers initialized before any remote store

    int p = 0;

    for (int t = 0; t < KT; ++t) {
        // ---- stage 1: two rows x one 38-k chunk; LDS.64 broadcast ----
        if (rp < 57) {
            const uint32_t hb = hbaseL + (uint32_t)(p * KBPC * KHP + k0) * 4;
            u64t A0 = 0, A1 = 0, A2 = 0, A3 = 0;   // row r0, batches 0..3
            u64t B0 = 0, B1 = 0, B2 = 0, B3 = 0;   // row r0+1
            #pragma unroll
            for (int i = 0; i < CPAIR; ++i) {
                const u64t h0 = lds_b64(hb + i * 8);
                const u64t h1 = lds_b64(hb + KHP * 4 + i * 8);
                const u64t h2 = lds_b64(hb + 2 * KHP * 4 + i * 8);
                const u64t h3 = lds_b64(hb + 3 * KHP * 4 + i * 8);
                const u64t wa = Wa[i], wb = Wb[i];
                fma2(A0, wa, h0); fma2(A1, wa, h1);
                fma2(A2, wa, h2); fma2(A3, wa, h3);
                fma2(B0, wb, h0); fma2(B1, wb, h1);
                fma2(B2, wb, h2); fma2(B3, wb, h3);
            }
            *reinterpret_cast<float4*>(&S.part[r0][c * 4]) =
                make_float4(hadd2(A0), hadd2(A1), hadd2(A2), hadd2(A3));
            *reinterpret_cast<float4*>(&S.part[r0 + 1][c * 4]) =
                make_float4(hadd2(B0), hadd2(B1), hadd2(B2), hadd2(B3));
        }
        __syncthreads();

        // ---- tail (warps 0-4, warp-uniform branch for shfl) ----
        if (tid < 160) {
            const int  jl    = jl_t;              // 0..39
            const int  m     = m_t;
            const bool valid = (jl < ucnt);
            const int  jlc   = valid ? jl : 0;    // clamped for safe reads

            const float* pR = S.part[jlc];
            const float* pZ = S.part[KU + jlc];
            const float* pN = S.part[2 * KU + jlc];
            float pr = 0.f, pz = 0.f, pn = 0.f;
            #pragma unroll
            for (int cc = 0; cc < NCH; ++cc) {
                pr += pR[cc * 4 + m];
                pz += pZ[cc * 4 + m];
                pn += pN[cc * 4 + m];
            }
            const float* gi = &S.gis[t & 1][0][0];
            const float r = sigm_fast(pr + gi[jlc * 4 + m]);
            const float z = sigm_fast(pz + gi[(KU + jlc) * 4 + m]);
            const float n = tanh_fast(gi[(2 * KU + jlc) * 4 + m]
                                      + r * (pn + S.bhhN[jlc]));
            float hn = (1.0f - z) * n + z * S.h[p][m][u0 + jlc];
            if (!valid) hn = 0.0f;

            // gather partner unit's hn (jl^1, same m): lanes tid^4
            const float hnB = __shfl_xor_sync(0xffffffffu, hn, 4);

            if (((jl & 1) == 0) && valid) {
                const u64t pairv = pack2(hn, hnB);   // {h[jl], h[jl+1]}
                const uint32_t off = p ? offB : offA;
                st_cluster_u64(R0 + off, pairv); st_cluster_u64(R1 + off, pairv);
                st_cluster_u64(R2 + off, pairv); st_cluster_u64(R3 + off, pairv);
                st_cluster_u64(R4 + off, pairv); st_cluster_u64(R5 + off, pairv);
                st_cluster_u64(R6 + off, pairv); st_cluster_u64(R7 + off, pairv);
            }
        }

        // ---- release this CTA's contribution; overlap shadow work ----
        asm volatile("barrier.cluster.arrive.aligned;" ::: "memory");

        if (tid >= 160 && tid < 160 + KBPC * KU) {
            // gi for step t+1 (h-independent) in the barrier shadow.
            if (t + 1 < KT) {
                const int idx = tid - 160;
                const int jl = idx >> 2, m = idx & 3;
                if (jl < ucnt) {
                    const float* xr = S.xs[(t + 1) & 1][m];
                    float gr = S.bsumF[jl], gz = S.bsumF[KU + jl],
                          gn = S.bsumF[2 * KU + jl];
                    #pragma unroll
                    for (int f = 0; f < KF; ++f) {
                        const float xf = xr[f];
                        gr = fmaf(S.WihT[f][jl], xf, gr);
                        gz = fmaf(S.WihT[f][KU + jl], xf, gz);
                        gn = fmaf(S.WihT[f][2 * KU + jl], xf, gn);
                    }
                    S.gis[(t + 1) & 1][jl][m] = gr;
                    S.gis[(t + 1) & 1][KU + jl][m] = gz;
                    S.gis[(t + 1) & 1][2 * KU + jl][m] = gn;
                }
            }
        } else if (tid >= 312 && tid < 312 + KBPC * KF) {
            // prefetch x_{t+2} into the xs slot freed this step
            if (t + 2 < KT) {
                const int idx = tid - 312;
                const int pm = idx / KF, pf = idx % KF;
                S.xs[(t + 2) & 1][pm][pf] =
                    x[((size_t)(cluster * KBPC + pm) * KT + (t + 2)) * KF + pf];
            }
        }

        asm volatile("barrier.cluster.wait.aligned;" ::: "memory");
        p ^= 1;
    }
    __syncthreads();

    // =======================================================================
    // Fused fc + relu + decoder: ranks 0-3 handle batch m = rank.
    // =======================================================================
    if (rank < KBPC) {
        const int m = rank;
        const int b = cluster * KBPC + m;
        float* embS = &S.part[0][0];       // 300 floats (reuse part scratch)
        float* dgiS = embS + 304;          // 39 floats

        const float* hrow = &S.h[p][m][0];
        for (int j = tid; j < KH; j += KTHR) {
            const float4* wr = reinterpret_cast<const float4*>(fcW + (size_t)j * KH);
            float s0 = 0.f, s1 = 0.f, s2 = 0.f, s3 = 0.f;
            #pragma unroll 5
            for (int k = 0; k < KH / 4; ++k) {
                const float4 w4 = wr[k];
                const float4 h4 = *reinterpret_cast<const float4*>(&hrow[k * 4]);
                s0 = fmaf(w4.x, h4.x, s0); s1 = fmaf(w4.y, h4.y, s1);
                s2 = fmaf(w4.z, h4.z, s2); s3 = fmaf(w4.w, h4.w, s3);
            }
            float s = fcb[j] + ((s0 + s1) + (s2 + s3));
            s = fmaxf(s, 0.0f);
            embS[j] = s;
            if (writeEmb)
                out[(size_t)KB * KT * KF + (size_t)b * KH + j] = s;
        }
        __syncthreads();

        if (tid < 3 * KF) {
            const float4* wr = reinterpret_cast<const float4*>(dWih + (size_t)tid * KH);
            float s0 = 0.f, s1 = 0.f, s2 = 0.f, s3 = 0.f;
            #pragma unroll 5
            for (int k = 0; k < KH / 4; ++k) {
                const float4 w4 = wr[k];
                const float4 h4 = *reinterpret_cast<const float4*>(&embS[k * 4]);
                s0 = fmaf(w4.x, h4.x, s0); s1 = fmaf(w4.y, h4.y, s1);
                s2 = fmaf(w4.z, h4.z, s2); s3 = fmaf(w4.w, h4.w, s3);
            }
            dgiS[tid] = dbih[tid] + ((s0 + s1) + (s2 + s3));
        }
        __syncthreads();

        if (tid < 32) {
            const int lane = tid;
            const bool act = (lane < KF);
            float wr_[KF], wz_[KF], wn_[KF];
            #pragma unroll
            for (int k = 0; k < KF; ++k) {
                wr_[k] = act ? dWhh[(size_t)lane * KF + k]            : 0.f;
                wz_[k] = act ? dWhh[(size_t)(KF + lane) * KF + k]     : 0.f;
                wn_[k] = act ? dWhh[(size_t)(2 * KF + lane) * KF + k] : 0.f;
            }
            const float bhr = act ? dbhh[lane]          : 0.f;
            const float bhz = act ? dbhh[KF + lane]     : 0.f;
            const float bhn = act ? dbhh[2 * KF + lane] : 0.f;
            const float dgr = act ? dgiS[lane]          : 0.f;
            const float dgz = act ? dgiS[KF + lane]     : 0.f;
            const float dgn = act ? dgiS[2 * KF + lane] : 0.f;
            float hv = 0.f;
            float* op = out + (size_t)b * KT * KF;

            for (int t = 0; t < KT; ++t) {
                float sr = bhr, sz = bhz, sn = bhn;
                #pragma unroll
                for (int k = 0; k < KF; ++k) {
                    const float hk = __shfl_sync(0xffffffffu, hv, k);
                    sr = fmaf(wr_[k], hk, sr);
                    sz = fmaf(wz_[k], hk, sz);
                    sn = fmaf(wn_[k], hk, sn);
                }
                if (act) {
                    const float r = sigm_fast(dgr + sr);
                    const float z = sigm_fast(dgz + sz);
                    const float n = tanh_fast(dgn + r * sn);
                    hv = (1.0f - z) * n + z * hv;
                    op[(size_t)t * KF + lane] = hv;
                }
            }
        }
    }
}

extern "C" void kernel_launch(void* const* d_in, const int* in_sizes, int n_in,
                              void* d_out, int out_size)
{
    const float* x    = (const float*)d_in[0];
    const float* eWih = (const float*)d_in[1];
    const float* eWhh = (const float*)d_in[2];
    const float* ebih = (const float*)d_in[3];
    const float* ebhh = (const float*)d_in[4];
    const float* fcW  = (const float*)d_in[5];
    const float* fcb  = (const float*)d_in[6];
    const float* dWih = (const float*)d_in[7];
    const float* dWhh = (const float*)d_in[8];
    const float* dbih = (const float*)d_in[9];
    const float* dbhh = (const float*)d_in[10];
    float* out = (float*)d_out;

    const int writeEmb = (out_size >= KB * KT * KF + KB * KH) ? 1 : 0;

    enc_kernel<<<(KB / KBPC) * KCL, KTHR>>>(
        x, eWih, eWhh, ebih, ebhh, fcW, fcb, dWih, dWhh, dbih, dbhh,
        out, writeEmb);
}